// round 8
// baseline (speedup 1.0000x reference)
#include <cuda_runtime.h>
#include <math.h>

#define B    16384
#define D    1024
#define KC   15
#define C    1000
#define NMOD 3

#define SEG_BY   148
#define SEG_ROWS 112   // 148*112 = 16576 >= B; all per-block lengths multiples of 8
#define CPAD     1024

// ---------------- scratch (device globals; no allocation) ----------------
__device__ float g_avg[NMOD][B];
__device__ int   g_assign[NMOD][B];
__device__ float g_probs[B][C];                    // normalized softmax probs
__device__ float g_part[NMOD * KC][SEG_BY][CPAD];  // per-block partial seg sums
__device__ float g_entpart[NMOD * KC];
__device__ float g_attrpart[NMOD];

// ---------------- softmax: stats + copy + normalized probs (side stream) --
__global__ __launch_bounds__(256) void softmax_kernel(const float* __restrict__ outp,
                                                      float* __restrict__ ocopy) {
    int warp = threadIdx.x >> 5, lane = threadIdx.x & 31;
    int row = blockIdx.x * 8 + warp;
    const float4* r4 = (const float4*)(outp + (size_t)row * C);
    float4* w4 = (float4*)(ocopy + (size_t)row * C);
    float4* p4 = (float4*)(&g_probs[row][0]);
    float4 a[8];
    float m = -INFINITY;
#pragma unroll
    for (int i = 0; i < 8; i++) {
        int j = lane + i * 32;
        if (j < C / 4) {
            float4 x = r4[j]; a[i] = x; w4[j] = x;
            m = fmaxf(m, fmaxf(fmaxf(x.x, x.y), fmaxf(x.z, x.w)));
        }
    }
#pragma unroll
    for (int o = 16; o > 0; o >>= 1) m = fmaxf(m, __shfl_xor_sync(0xffffffffu, m, o));
    float s = 0.f;
#pragma unroll
    for (int i = 0; i < 8; i++) {
        int j = lane + i * 32;
        if (j < C / 4) {
            a[i].x = __expf(a[i].x - m); a[i].y = __expf(a[i].y - m);
            a[i].z = __expf(a[i].z - m); a[i].w = __expf(a[i].w - m);
            s += a[i].x + a[i].y + a[i].z + a[i].w;
        }
    }
#pragma unroll
    for (int o = 16; o > 0; o >>= 1) s += __shfl_xor_sync(0xffffffffu, s, o);
    float ri = 1.f / s;
#pragma unroll
    for (int i = 0; i < 8; i++) {
        int j = lane + i * 32;
        if (j < C / 4) {
            float4 x = a[i];
            x.x *= ri; x.y *= ri; x.z *= ri; x.w *= ri;
            p4[j] = x;
        }
    }
}

// ---------------- similarities (butterfly) + in-block centroid norms ------
#define SIM_ROWS 32
__global__ __launch_bounds__(256, 2) void sim_kernel(
    const float* __restrict__ f0, const float* __restrict__ f1, const float* __restrict__ f2,
    const float* __restrict__ c0, const float* __restrict__ c1, const float* __restrict__ c2) {
    int mod = blockIdx.y;
    const float* fea = mod == 0 ? f0 : (mod == 1 ? f1 : f2);
    const float* cen = mod == 0 ? c0 : (mod == 1 ? c1 : c2);
    int tid = threadIdx.x;
    int lane = tid & 31, warp = tid >> 5;
    int col = tid * 4;

    float4 cw[KC];
#pragma unroll
    for (int k = 0; k < KC; k++)
        cw[k] = *(const float4*)(cen + (size_t)k * D + col);

    __shared__ float stage[SIM_ROWS][8][16];   // 16 KB
    __shared__ float tot[SIM_ROWS][16];        // 2 KB
    __shared__ float s_cn[KC];

    int vidx = ((lane & 1) ? 8 : 0) | ((lane & 2) ? 4 : 0) |
               ((lane & 4) ? 2 : 0) | ((lane & 8) ? 1 : 0);

    // ---- centroid norms from register-resident tile ----
    {
        float v[16];
        v[15] = 0.f;
#pragma unroll
        for (int k = 0; k < KC; k++)
            v[k] = cw[k].x * cw[k].x + cw[k].y * cw[k].y + cw[k].z * cw[k].z + cw[k].w * cw[k].w;
#pragma unroll
        for (int s = 0; s < 4; s++) {
            int d2 = 1 << s, half = 8 >> s;
            bool hi = (lane & d2) != 0;
#pragma unroll
            for (int i = 0; i < half; i++) {
                float send = hi ? v[i] : v[i + half];
                float recv = __shfl_xor_sync(0xffffffffu, send, d2);
                v[i] = (hi ? v[i + half] : v[i]) + recv;
            }
        }
        v[0] += __shfl_xor_sync(0xffffffffu, v[0], 16);
        if (lane < 16) stage[0][warp][vidx] = v[0];
        __syncthreads();
        if (tid < KC) {
            float s = 0.f;
#pragma unroll
            for (int w = 0; w < 8; w++) s += stage[0][w][tid];
            s_cn[tid] = 1.f / fmaxf(sqrtf(s), 1e-12f);
        }
        __syncthreads();
    }

    int row0 = blockIdx.x * SIM_ROWS;
    const float4* fp = (const float4*)(fea + (size_t)row0 * D) + tid;
    float4 f = fp[0];

    for (int rr = 0; rr < SIM_ROWS; rr++) {
        float4 fn;
        if (rr + 1 < SIM_ROWS) fn = fp[(rr + 1) * (D / 4)];

        float v[16];
        v[15] = f.x * f.x + f.y * f.y + f.z * f.z + f.w * f.w;
#pragma unroll
        for (int k = 0; k < KC; k++)
            v[k] = f.x * cw[k].x + f.y * cw[k].y + f.z * cw[k].z + f.w * cw[k].w;

#pragma unroll
        for (int s = 0; s < 4; s++) {
            int d2 = 1 << s, half = 8 >> s;
            bool hi = (lane & d2) != 0;
#pragma unroll
            for (int i = 0; i < half; i++) {
                float send = hi ? v[i] : v[i + half];
                float recv = __shfl_xor_sync(0xffffffffu, send, d2);
                v[i] = (hi ? v[i + half] : v[i]) + recv;
            }
        }
        v[0] += __shfl_xor_sync(0xffffffffu, v[0], 16);

        if (lane < 16) stage[rr][warp][vidx] = v[0];
        f = fn;
    }
    __syncthreads();

#pragma unroll
    for (int e = tid; e < SIM_ROWS * 16; e += 256) {
        int r = e >> 4, vv = e & 15;
        float s = 0.f;
#pragma unroll
        for (int w = 0; w < 8; w++) s += stage[r][w][vv];
        tot[r][vv] = s;
    }
    __syncthreads();

    if (tid < SIM_ROWS) {
        int r = tid;
        float fin = 1.f / fmaxf(sqrtf(tot[r][15]), 1e-12f);
        float best = -1e30f; int bi = 0; float sum = 0.f;
#pragma unroll
        for (int k = 0; k < KC; k++) {
            float sim = tot[r][k] * fin * s_cn[k];
            sum += sim;
            if (sim > best) { best = sim; bi = k; }
        }
        g_avg[mod][row0 + r] = sum * (1.0f / KC);
        g_assign[mod][row0 + r] = bi;
    }
}

// ---------------- radix select + attractive (smem-resident, side stream) --
__global__ __launch_bounds__(1024) void select_attr_kernel(int rank0) {
    extern __shared__ unsigned int skeys[];       // 16384 u32 = 64 KB
    __shared__ unsigned int hist[256];
    __shared__ unsigned int sc[256];
    __shared__ unsigned int s_prefix;
    __shared__ int s_rank;
    __shared__ float s_thr;
    __shared__ float sred[32];

    int mod = blockIdx.x;
    const float* avg = g_avg[mod];
    int tid = threadIdx.x;
    int lane = tid & 31, warp = tid >> 5;

#pragma unroll
    for (int i = tid; i < B; i += 1024) {
        unsigned int u = __float_as_uint(avg[i]);
        skeys[i] = (u & 0x80000000u) ? ~u : (u | 0x80000000u);
    }
    if (tid == 0) { s_prefix = 0u; s_rank = rank0; }
    __syncthreads();

    for (int p = 3; p >= 0; p--) {
        if (tid < 256) hist[tid] = 0u;
        __syncthreads();
        unsigned int mask = (p == 3) ? 0u : (0xFFFFFFFFu << ((p + 1) * 8));
        unsigned int pref = s_prefix;
        int r = s_rank;
#pragma unroll
        for (int i = tid; i < B; i += 1024) {
            unsigned int u = skeys[i];
            if ((u & mask) == (pref & mask))
                atomicAdd(&hist[(u >> (p * 8)) & 255u], 1u);
        }
        __syncthreads();
        if (tid < 256) sc[tid] = hist[tid];
        __syncthreads();
#pragma unroll
        for (int off = 1; off < 256; off <<= 1) {
            unsigned int add = 0u;
            if (tid < 256 && tid >= off) add = sc[tid - off];
            __syncthreads();
            if (tid < 256) sc[tid] += add;
            __syncthreads();
        }
        if (tid < 256) {
            unsigned int inc = sc[tid], exc = inc - hist[tid];
            if ((unsigned int)r >= exc && (unsigned int)r < inc) {
                s_prefix = pref | ((unsigned int)tid << (p * 8));
                s_rank = r - (int)exc;
            }
        }
        __syncthreads();
    }
    if (tid == 0) {
        unsigned int u = s_prefix;
        unsigned int bits = (u & 0x80000000u) ? (u ^ 0x80000000u) : ~u;
        s_thr = __uint_as_float(bits);
    }
    __syncthreads();

    float thr = s_thr;
    float s = 0.f;
#pragma unroll
    for (int i = tid; i < B; i += 1024) {
        unsigned int u = skeys[i];
        unsigned int bits = (u & 0x80000000u) ? (u ^ 0x80000000u) : ~u;
        float a = __uint_as_float(bits);
        float w = 1.f / (1.f + expf(-5.0f * (a - thr)));   // ALPHA = 5
        s += w * (1.f - a);
    }
#pragma unroll
    for (int o = 16; o > 0; o >>= 1) s += __shfl_xor_sync(0xffffffffu, s, o);
    if (lane == 0) sred[warp] = s;
    __syncthreads();
    if (tid < 32) {
        float t = sred[tid];
#pragma unroll
        for (int o = 16; o > 0; o >>= 1) t += __shfl_xor_sync(0xffffffffu, t, o);
        if (tid == 0) g_attrpart[mod] = t;
    }
}

// ---------------- segment partial sums: pure gather-accumulate ------------
// grid (4, 148) = 4 blocks/SM; no exp, no division; MLP=8 loads in flight.
#define SEG_CHUNK 64
__global__ __launch_bounds__(256, 4) void seg_kernel() {
    __shared__ float acc[NMOD * KC * 256];   // 46080 B
    __shared__ int   s_a0[SEG_CHUNK], s_a1[SEG_CHUNK], s_a2[SEG_CHUNK];
    int tid = threadIdx.x;
    int c = blockIdx.x * 256 + tid;
    bool valid = c < C;
    for (int j = tid; j < NMOD * KC * 256; j += 256) acc[j] = 0.f;

    int r0 = blockIdx.y * SEG_ROWS;
    int rend = r0 + SEG_ROWS; if (rend > B) rend = B;

    for (int cb = r0; cb < rend; cb += SEG_CHUNK) {
        int clen = rend - cb; if (clen > SEG_CHUNK) clen = SEG_CHUNK;  // multiple of 8
        __syncthreads();
        if (tid < clen) {
            s_a0[tid] = g_assign[0][cb + tid] * 256;
            s_a1[tid] = (KC + g_assign[1][cb + tid]) * 256;
            s_a2[tid] = (2 * KC + g_assign[2][cb + tid]) * 256;
        }
        __syncthreads();
        if (valid) {
            const float* pp = &g_probs[cb][0] + c;
            for (int rr = 0; rr < clen; rr += 8) {
                float p[8];
#pragma unroll
                for (int j = 0; j < 8; j++)
                    p[j] = pp[(size_t)(rr + j) * C];           // 8 loads in flight
#pragma unroll
                for (int j = 0; j < 8; j++) {
                    acc[s_a0[rr + j] + tid] += p[j];
                    acc[s_a1[rr + j] + tid] += p[j];
                    acc[s_a2[rr + j] + tid] += p[j];
                }
            }
        }
    }
    __syncthreads();
    if (valid) {
        int by = blockIdx.y;
#pragma unroll
        for (int j = 0; j < NMOD * KC; j++)
            g_part[j][by][c] = acc[j * 256 + tid];
    }
}

// ---------------- gated entropy (counts computed in-block) ----------------
__global__ void entropy_kernel() {
    int bk = blockIdx.x;  // 0..44
    int mod = bk / KC, k = bk % KC;
    int tid = threadIdx.x;

    int cnt = 0;
    const int* as = g_assign[mod];
    for (int i = tid; i < B; i += 256) cnt += (as[i] == k);
    __shared__ int ci[256];
    ci[tid] = cnt; __syncthreads();
    for (int o = 128; o > 0; o >>= 1) {
        if (tid < o) ci[tid] += ci[tid + o];
        __syncthreads();
    }
    float fcnt = (float)ci[0];
    float inv = 1.f / fmaxf(fcnt, 1.f);

    const float* base = &g_part[bk][0][0];
    float s = 0.f;
    for (int i = tid; i < C; i += 256) {
        float t = 0.f;
#pragma unroll 4
        for (int by = 0; by < SEG_BY; by++) t += base[(size_t)by * CPAD + i];
        float mp = t * inv;
        s += mp * __logf(mp + 1e-8f);
    }
    __shared__ float sm[256];
    sm[tid] = s; __syncthreads();
    for (int o = 128; o > 0; o >>= 1) {
        if (tid < o) sm[tid] += sm[tid + o];
        __syncthreads();
    }
    if (tid == 0) g_entpart[bk] = (fcnt >= 3.0f) ? sm[0] : 0.f;
}

// ---------------- finalize ----------------
__global__ void finalize_kernel(float* dout_last) {
    int lane = threadIdx.x;   // 64 threads
    float s = (lane < NMOD * KC) ? g_entpart[lane] : 0.f;
#pragma unroll
    for (int o = 16; o > 0; o >>= 1) s += __shfl_xor_sync(0xffffffffu, s, o);
    __shared__ float w0, w1;
    if (lane == 0) w0 = s;
    if (lane == 32) w1 = s;
    __syncthreads();
    if (lane == 0) {
        float attr = g_attrpart[0] + g_attrpart[1] + g_attrpart[2];
        // LAM_CLUSTER = 6.0, LAM_DIV = 0.1
        *dout_last = 6.0f * (attr / (float)B) + 0.1f * (w0 + w1);
    }
}

// ---------------- launch: fork-join multi-stream graph --------------------
extern "C" void kernel_launch(void* const* d_in, const int* in_sizes, int n_in,
                              void* d_out, int out_size) {
    const float* f0 = (const float*)d_in[0];
    const float* f1 = (const float*)d_in[1];
    const float* f2 = (const float*)d_in[2];
    const float* c0 = (const float*)d_in[3];
    const float* c1 = (const float*)d_in[4];
    const float* c2 = (const float*)d_in[5];
    const float* outp = (const float*)d_in[6];
    float* dout = (float*)d_out;
    (void)n_in; (void)in_sizes;

    static cudaStream_t s1 = 0, s2 = 0;
    static cudaEvent_t ev_root = 0, ev_sm = 0, ev_sim = 0, ev_sel = 0;
    if (s1 == 0) {
        cudaStreamCreateWithFlags(&s1, cudaStreamNonBlocking);
        cudaStreamCreateWithFlags(&s2, cudaStreamNonBlocking);
        cudaEventCreateWithFlags(&ev_root, cudaEventDisableTiming);
        cudaEventCreateWithFlags(&ev_sm, cudaEventDisableTiming);
        cudaEventCreateWithFlags(&ev_sim, cudaEventDisableTiming);
        cudaEventCreateWithFlags(&ev_sel, cudaEventDisableTiming);
        cudaFuncSetAttribute(select_attr_kernel,
                             cudaFuncAttributeMaxDynamicSharedMemorySize, B * 4);
    }

    // fork: softmax+probs on s1 (independent of sim)
    cudaEventRecord(ev_root, 0);
    cudaStreamWaitEvent(s1, ev_root, 0);
    softmax_kernel<<<B / 8, 256, 0, s1>>>(outp, dout);                      // #1
    cudaEventRecord(ev_sm, s1);

    // main: sim (with fused centroid norms)
    sim_kernel<<<dim3(B / SIM_ROWS, NMOD), 256>>>(f0, f1, f2, c0, c1, c2);  // #2

    // fork: select on s2 (depends only on sim)
    cudaEventRecord(ev_sim, 0);
    cudaStreamWaitEvent(s2, ev_sim, 0);
    int rank0 = B - (int)((double)B * 0.6);   // = 6554
    select_attr_kernel<<<NMOD, 1024, B * 4, s2>>>(rank0);                   // #3
    cudaEventRecord(ev_sel, s2);

    // main: seg needs probs + assigns
    cudaStreamWaitEvent(0, ev_sm, 0);
    seg_kernel<<<dim3(4, SEG_BY), 256>>>();                                 // #4 (profiled)
    entropy_kernel<<<NMOD * KC, 256>>>();                                   // #5

    cudaStreamWaitEvent(0, ev_sel, 0);
    finalize_kernel<<<1, 64>>>(dout + (size_t)out_size - 1);                // #6
}

// round 9
// speedup vs baseline: 1.5396x; 1.5396x over previous
#include <cuda_runtime.h>
#include <math.h>

#define B    16384
#define D    1024
#define KC   15
#define C    1000
#define NMOD 3

#define SEG_ROWS 112   // grid (4,148): 148*112 = 16576 >= B; multiples of 8

// ---------------- scratch (device globals; no allocation) ----------------
__device__ float g_avg[NMOD][B];
__device__ int   g_assign[NMOD][B];
__device__ float g_rmax[B];
__device__ float g_rinv[B];
__device__ float g_segsum[NMOD * KC][C];   // 180 KB, L2-resident
__device__ float g_entpart[NMOD * KC];
__device__ float g_attrpart[NMOD];
__device__ int   g_ticket;

// ---------------- #1 (s1): zero segsum + ticket ----------------
__global__ void init_kernel() {
    int i = blockIdx.x * blockDim.x + threadIdx.x;
    if (i < NMOD * KC * C) ((float*)g_segsum)[i] = 0.f;
    if (i == 0) g_ticket = 0;
}

// ---------------- #2 (s1): softmax stats only (light) ----------------
__global__ __launch_bounds__(256) void stats_kernel(const float* __restrict__ outp) {
    int warp = threadIdx.x >> 5, lane = threadIdx.x & 31;
    int row = blockIdx.x * 8 + warp;
    const float4* r4 = (const float4*)(outp + (size_t)row * C);
    float4 a[8];
    float m = -INFINITY;
#pragma unroll
    for (int i = 0; i < 8; i++) {
        int j = lane + i * 32;
        if (j < C / 4) {
            float4 x = r4[j]; a[i] = x;
            m = fmaxf(m, fmaxf(fmaxf(x.x, x.y), fmaxf(x.z, x.w)));
        }
    }
#pragma unroll
    for (int o = 16; o > 0; o >>= 1) m = fmaxf(m, __shfl_xor_sync(0xffffffffu, m, o));
    float s = 0.f;
#pragma unroll
    for (int i = 0; i < 8; i++) {
        int j = lane + i * 32;
        if (j < C / 4)
            s += __expf(a[i].x - m) + __expf(a[i].y - m) + __expf(a[i].z - m) + __expf(a[i].w - m);
    }
#pragma unroll
    for (int o = 16; o > 0; o >>= 1) s += __shfl_xor_sync(0xffffffffu, s, o);
    if (lane == 0) { g_rmax[row] = m; g_rinv[row] = 1.f / s; }
}

// ---------------- #3 (s1): pure copy out -> d_out ----------------
__global__ __launch_bounds__(256) void copy_kernel(const float* __restrict__ src,
                                                   float* __restrict__ dst) {
    size_t i = (size_t)blockIdx.x * 256 + threadIdx.x;
    size_t n4 = (size_t)B * C / 4;
    const float4* s4 = (const float4*)src;
    float4* d4 = (float4*)dst;
    for (; i < n4; i += (size_t)gridDim.x * 256) d4[i] = s4[i];
}

// ---------------- #4 (main, PROFILED): similarities, 2-row interleaved ----
#define SIM_ROWS 32
__global__ __launch_bounds__(256, 2) void sim_kernel(
    const float* __restrict__ f0, const float* __restrict__ f1, const float* __restrict__ f2,
    const float* __restrict__ c0, const float* __restrict__ c1, const float* __restrict__ c2) {
    int mod = blockIdx.y;
    const float* fea = mod == 0 ? f0 : (mod == 1 ? f1 : f2);
    const float* cen = mod == 0 ? c0 : (mod == 1 ? c1 : c2);
    int tid = threadIdx.x;
    int lane = tid & 31, warp = tid >> 5;
    int col = tid * 4;

    float4 cw[KC];
#pragma unroll
    for (int k = 0; k < KC; k++)
        cw[k] = *(const float4*)(cen + (size_t)k * D + col);

    __shared__ float stage[SIM_ROWS][8][16];   // 16 KB
    __shared__ float tot[SIM_ROWS][16];        // 2 KB
    __shared__ float s_cn[KC];

    int vidx = ((lane & 1) ? 8 : 0) | ((lane & 2) ? 4 : 0) |
               ((lane & 4) ? 2 : 0) | ((lane & 8) ? 1 : 0);

    // ---- centroid norms from register-resident tile ----
    {
        float v[16];
        v[15] = 0.f;
#pragma unroll
        for (int k = 0; k < KC; k++)
            v[k] = cw[k].x * cw[k].x + cw[k].y * cw[k].y + cw[k].z * cw[k].z + cw[k].w * cw[k].w;
#pragma unroll
        for (int s = 0; s < 4; s++) {
            int d2 = 1 << s, half = 8 >> s;
            bool hi = (lane & d2) != 0;
#pragma unroll
            for (int i = 0; i < half; i++) {
                float send = hi ? v[i] : v[i + half];
                float recv = __shfl_xor_sync(0xffffffffu, send, d2);
                v[i] = (hi ? v[i + half] : v[i]) + recv;
            }
        }
        v[0] += __shfl_xor_sync(0xffffffffu, v[0], 16);
        if (lane < 16) stage[0][warp][vidx] = v[0];
        __syncthreads();
        if (tid < KC) {
            float s = 0.f;
#pragma unroll
            for (int w = 0; w < 8; w++) s += stage[0][w][tid];
            s_cn[tid] = 1.f / fmaxf(sqrtf(s), 1e-12f);
        }
        __syncthreads();
    }

    int row0 = blockIdx.x * SIM_ROWS;
    const float4* fp = (const float4*)(fea + (size_t)row0 * D) + tid;
    float4 fa = fp[0];
    float4 fb = fp[D / 4];

    // -------- mainloop: 2 rows per iteration, interleaved butterflies -----
    for (int rr = 0; rr < SIM_ROWS; rr += 2) {
        float4 na, nb;
        if (rr + 2 < SIM_ROWS) {
            na = fp[(rr + 2) * (D / 4)];
            nb = fp[(rr + 3) * (D / 4)];
        }

        float va[16], vb[16];
        va[15] = fa.x * fa.x + fa.y * fa.y + fa.z * fa.z + fa.w * fa.w;
        vb[15] = fb.x * fb.x + fb.y * fb.y + fb.z * fb.z + fb.w * fb.w;
#pragma unroll
        for (int k = 0; k < KC; k++) {
            va[k] = fa.x * cw[k].x + fa.y * cw[k].y + fa.z * cw[k].z + fa.w * cw[k].w;
            vb[k] = fb.x * cw[k].x + fb.y * cw[k].y + fb.z * cw[k].z + fb.w * cw[k].w;
        }

#pragma unroll
        for (int s = 0; s < 4; s++) {
            int d2 = 1 << s, half = 8 >> s;
            bool hi = (lane & d2) != 0;
#pragma unroll
            for (int i = 0; i < half; i++) {
                float sa = hi ? va[i] : va[i + half];
                float sb = hi ? vb[i] : vb[i + half];
                float ra = __shfl_xor_sync(0xffffffffu, sa, d2);
                float rb = __shfl_xor_sync(0xffffffffu, sb, d2);
                va[i] = (hi ? va[i + half] : va[i]) + ra;
                vb[i] = (hi ? vb[i + half] : vb[i]) + rb;
            }
        }
        va[0] += __shfl_xor_sync(0xffffffffu, va[0], 16);
        vb[0] += __shfl_xor_sync(0xffffffffu, vb[0], 16);

        if (lane < 16) {
            stage[rr][warp][vidx]     = va[0];
            stage[rr + 1][warp][vidx] = vb[0];
        }
        fa = na; fb = nb;
    }
    __syncthreads();

    // -------- reduce over warps --------
#pragma unroll
    for (int e = tid; e < SIM_ROWS * 16; e += 256) {
        int r = e >> 4, vv = e & 15;
        float s = 0.f;
#pragma unroll
        for (int w = 0; w < 8; w++) s += stage[r][w][vv];
        tot[r][vv] = s;
    }
    __syncthreads();

    // -------- finalize, one thread per row --------
    if (tid < SIM_ROWS) {
        int r = tid;
        float fin = 1.f / fmaxf(sqrtf(tot[r][15]), 1e-12f);
        float best = -1e30f; int bi = 0; float sum = 0.f;
#pragma unroll
        for (int k = 0; k < KC; k++) {
            float sim = tot[r][k] * fin * s_cn[k];
            sum += sim;
            if (sim > best) { best = sim; bi = k; }
        }
        g_avg[mod][row0 + r] = sum * (1.0f / KC);
        g_assign[mod][row0 + r] = bi;
    }
}

// ---------------- #5 (s2): radix select + attractive (smem-resident) ------
__global__ __launch_bounds__(1024) void select_attr_kernel(int rank0) {
    extern __shared__ unsigned int skeys[];       // 16384 u32 = 64 KB
    __shared__ unsigned int hist[256];
    __shared__ unsigned int sc[256];
    __shared__ unsigned int s_prefix;
    __shared__ int s_rank;
    __shared__ float s_thr;
    __shared__ float sred[32];

    int mod = blockIdx.x;
    const float* avg = g_avg[mod];
    int tid = threadIdx.x;
    int lane = tid & 31, warp = tid >> 5;

#pragma unroll
    for (int i = tid; i < B; i += 1024) {
        unsigned int u = __float_as_uint(avg[i]);
        skeys[i] = (u & 0x80000000u) ? ~u : (u | 0x80000000u);
    }
    if (tid == 0) { s_prefix = 0u; s_rank = rank0; }
    __syncthreads();

    for (int p = 3; p >= 0; p--) {
        if (tid < 256) hist[tid] = 0u;
        __syncthreads();
        unsigned int mask = (p == 3) ? 0u : (0xFFFFFFFFu << ((p + 1) * 8));
        unsigned int pref = s_prefix;
        int r = s_rank;
#pragma unroll
        for (int i = tid; i < B; i += 1024) {
            unsigned int u = skeys[i];
            if ((u & mask) == (pref & mask))
                atomicAdd(&hist[(u >> (p * 8)) & 255u], 1u);
        }
        __syncthreads();
        if (tid < 256) sc[tid] = hist[tid];
        __syncthreads();
#pragma unroll
        for (int off = 1; off < 256; off <<= 1) {
            unsigned int add = 0u;
            if (tid < 256 && tid >= off) add = sc[tid - off];
            __syncthreads();
            if (tid < 256) sc[tid] += add;
            __syncthreads();
        }
        if (tid < 256) {
            unsigned int inc = sc[tid], exc = inc - hist[tid];
            if ((unsigned int)r >= exc && (unsigned int)r < inc) {
                s_prefix = pref | ((unsigned int)tid << (p * 8));
                s_rank = r - (int)exc;
            }
        }
        __syncthreads();
    }
    if (tid == 0) {
        unsigned int u = s_prefix;
        unsigned int bits = (u & 0x80000000u) ? (u ^ 0x80000000u) : ~u;
        s_thr = __uint_as_float(bits);
    }
    __syncthreads();

    float thr = s_thr;
    float s = 0.f;
#pragma unroll
    for (int i = tid; i < B; i += 1024) {
        unsigned int u = skeys[i];
        unsigned int bits = (u & 0x80000000u) ? (u ^ 0x80000000u) : ~u;
        float a = __uint_as_float(bits);
        float w = 1.f / (1.f + expf(-5.0f * (a - thr)));   // ALPHA = 5
        s += w * (1.f - a);
    }
#pragma unroll
    for (int o = 16; o > 0; o >>= 1) s += __shfl_xor_sync(0xffffffffu, s, o);
    if (lane == 0) sred[warp] = s;
    __syncthreads();
    if (tid < 32) {
        float t = sred[tid];
#pragma unroll
        for (int o = 16; o > 0; o >>= 1) t += __shfl_xor_sync(0xffffffffu, t, o);
        if (tid == 0) g_attrpart[mod] = t;
    }
}

// ---------------- #6 (main): segment sums, exp in-kernel, L2 atomics ------
#define SEG_CHUNK 64
__global__ __launch_bounds__(256, 4) void seg_kernel(const float* __restrict__ outp) {
    __shared__ float acc[NMOD * KC * 256];   // 46080 B
    __shared__ int   s_a0[SEG_CHUNK], s_a1[SEG_CHUNK], s_a2[SEG_CHUNK];
    __shared__ float s_rm[SEG_CHUNK], s_ri[SEG_CHUNK];
    int tid = threadIdx.x;
    int c = blockIdx.x * 256 + tid;
    bool valid = c < C;
    for (int j = tid; j < NMOD * KC * 256; j += 256) acc[j] = 0.f;

    int r0 = blockIdx.y * SEG_ROWS;
    int rend = r0 + SEG_ROWS; if (rend > B) rend = B;

    for (int cb = r0; cb < rend; cb += SEG_CHUNK) {
        int clen = rend - cb; if (clen > SEG_CHUNK) clen = SEG_CHUNK;  // mult of 8
        __syncthreads();
        if (tid < clen) {
            s_a0[tid] = g_assign[0][cb + tid] * 256;
            s_a1[tid] = (KC + g_assign[1][cb + tid]) * 256;
            s_a2[tid] = (2 * KC + g_assign[2][cb + tid]) * 256;
            s_rm[tid] = g_rmax[cb + tid];
            s_ri[tid] = g_rinv[cb + tid];
        }
        __syncthreads();
        if (valid) {
            const float* op = outp + (size_t)cb * C + c;
            for (int rr = 0; rr < clen; rr += 8) {
                float p[8];
#pragma unroll
                for (int j = 0; j < 8; j++)
                    p[j] = op[(size_t)(rr + j) * C];           // 8 loads in flight
#pragma unroll
                for (int j = 0; j < 8; j++)
                    p[j] = __expf(p[j] - s_rm[rr + j]) * s_ri[rr + j];
#pragma unroll
                for (int j = 0; j < 8; j++) {
                    acc[s_a0[rr + j] + tid] += p[j];
                    acc[s_a1[rr + j] + tid] += p[j];
                    acc[s_a2[rr + j] + tid] += p[j];
                }
            }
        }
    }
    __syncthreads();
    if (valid) {
#pragma unroll
        for (int j = 0; j < NMOD * KC; j++)
            atomicAdd(&g_segsum[j][c], acc[j * 256 + tid]);    // L2-resident
    }
}

// ---------------- #7 (main): entropy + counts + finalize (ticket) ---------
__global__ void entropy_final_kernel(float* dout_last) {
    int bk = blockIdx.x;  // 0..44
    int mod = bk / KC, k = bk % KC;
    int tid = threadIdx.x;

    int cnt = 0;
    const int* as = g_assign[mod];
    for (int i = tid; i < B; i += 256) cnt += (as[i] == k);
    __shared__ int ci[256];
    ci[tid] = cnt; __syncthreads();
    for (int o = 128; o > 0; o >>= 1) {
        if (tid < o) ci[tid] += ci[tid + o];
        __syncthreads();
    }
    float fcnt = (float)ci[0];
    float inv = 1.f / fmaxf(fcnt, 1.f);

    float s = 0.f;
    for (int i = tid; i < C; i += 256) {
        float mp = g_segsum[bk][i] * inv;
        s += mp * __logf(mp + 1e-8f);
    }
    __shared__ float sm[256];
    sm[tid] = s; __syncthreads();
    for (int o = 128; o > 0; o >>= 1) {
        if (tid < o) sm[tid] += sm[tid + o];
        __syncthreads();
    }
    if (tid == 0) {
        g_entpart[bk] = (fcnt >= 3.0f) ? sm[0] : 0.f;
        __threadfence();
        int t = atomicAdd(&g_ticket, 1);
        if (t == NMOD * KC - 1) {
            __threadfence();
            float div = 0.f;
#pragma unroll
            for (int j = 0; j < NMOD * KC; j++) div += g_entpart[j];
            float attr = g_attrpart[0] + g_attrpart[1] + g_attrpart[2];
            // LAM_CLUSTER = 6.0, LAM_DIV = 0.1
            *dout_last = 6.0f * (attr / (float)B) + 0.1f * div;
        }
    }
}

// ---------------- launch: fork-join multi-stream graph --------------------
extern "C" void kernel_launch(void* const* d_in, const int* in_sizes, int n_in,
                              void* d_out, int out_size) {
    const float* f0 = (const float*)d_in[0];
    const float* f1 = (const float*)d_in[1];
    const float* f2 = (const float*)d_in[2];
    const float* c0 = (const float*)d_in[3];
    const float* c1 = (const float*)d_in[4];
    const float* c2 = (const float*)d_in[5];
    const float* outp = (const float*)d_in[6];
    float* dout = (float*)d_out;
    (void)n_in; (void)in_sizes;

    static cudaStream_t s1 = 0, s2 = 0;
    static cudaEvent_t ev_root = 0, ev_stats = 0, ev_copy = 0, ev_sim = 0, ev_sel = 0;
    if (s1 == 0) {
        cudaStreamCreateWithFlags(&s1, cudaStreamNonBlocking);
        cudaStreamCreateWithFlags(&s2, cudaStreamNonBlocking);
        cudaEventCreateWithFlags(&ev_root, cudaEventDisableTiming);
        cudaEventCreateWithFlags(&ev_stats, cudaEventDisableTiming);
        cudaEventCreateWithFlags(&ev_copy, cudaEventDisableTiming);
        cudaEventCreateWithFlags(&ev_sim, cudaEventDisableTiming);
        cudaEventCreateWithFlags(&ev_sel, cudaEventDisableTiming);
        cudaFuncSetAttribute(select_attr_kernel,
                             cudaFuncAttributeMaxDynamicSharedMemorySize, B * 4);
    }

    // fork to s1: init + stats + copy (all independent of sim)
    cudaEventRecord(ev_root, 0);
    cudaStreamWaitEvent(s1, ev_root, 0);
    init_kernel<<<(NMOD * KC * C + 255) / 256, 256, 0, s1>>>();             // #1
    stats_kernel<<<B / 8, 256, 0, s1>>>(outp);                              // #2
    cudaEventRecord(ev_stats, s1);
    copy_kernel<<<2048, 256, 0, s1>>>(outp, dout);                          // #3
    cudaEventRecord(ev_copy, s1);

    // main: sim (profiled slot #4)
    sim_kernel<<<dim3(B / SIM_ROWS, NMOD), 256>>>(f0, f1, f2, c0, c1, c2);  // #4

    // fork to s2: select (depends only on sim)
    cudaEventRecord(ev_sim, 0);
    cudaStreamWaitEvent(s2, ev_sim, 0);
    int rank0 = B - (int)((double)B * 0.6);   // = 6554
    select_attr_kernel<<<NMOD, 1024, B * 4, s2>>>(rank0);                   // #5
    cudaEventRecord(ev_sel, s2);

    // main: seg needs stats(+init) + assigns(sim on same stream)
    cudaStreamWaitEvent(0, ev_stats, 0);
    seg_kernel<<<dim3(4, 148), 256>>>(outp);                                // #6

    // join select + copy, then entropy+finalize
    cudaStreamWaitEvent(0, ev_sel, 0);
    cudaStreamWaitEvent(0, ev_copy, 0);
    entropy_final_kernel<<<NMOD * KC, 256>>>(dout + (size_t)out_size - 1);  // #7
}

// round 10
// speedup vs baseline: 1.9485x; 1.2656x over previous
#include <cuda_runtime.h>
#include <math.h>

#define B    16384
#define D    1024
#define KC   15
#define C    1000
#define NMOD 3

#define SEG_ROWS 112   // grid (4,148): 148*112 = 16576 >= B; multiples of 8

// ---------------- scratch (device globals; no allocation) ----------------
__device__ float g_avg[NMOD][B];
__device__ int   g_assign[NMOD][B];
__device__ float g_rmax[B];
__device__ float g_rinv[B];
__device__ float g_segsum[NMOD * KC][C];   // 180 KB, L2-resident
__device__ float g_entpart[NMOD * KC];
__device__ float g_attrpart[NMOD];
__device__ int   g_ticket;

__device__ __forceinline__ unsigned f2tf32(float x) {
    unsigned r; asm("cvt.rna.tf32.f32 %0, %1;" : "=r"(r) : "f"(x)); return r;
}
__device__ __forceinline__ void mma_tf32(float c[4], unsigned a0, unsigned a1,
                                         unsigned a2, unsigned a3,
                                         unsigned b0, unsigned b1) {
    asm volatile(
        "mma.sync.aligned.m16n8k8.row.col.f32.tf32.tf32.f32 "
        "{%0,%1,%2,%3}, {%4,%5,%6,%7}, {%8,%9}, {%0,%1,%2,%3};\n"
        : "+f"(c[0]), "+f"(c[1]), "+f"(c[2]), "+f"(c[3])
        : "r"(a0), "r"(a1), "r"(a2), "r"(a3), "r"(b0), "r"(b1));
}

// ---------------- #1 (s1): zero segsum + ticket ----------------
__global__ void init_kernel() {
    int i = blockIdx.x * blockDim.x + threadIdx.x;
    if (i < NMOD * KC * C) ((float*)g_segsum)[i] = 0.f;
    if (i == 0) g_ticket = 0;
}

// ---------------- #2 (s1): softmax stats only ----------------
__global__ __launch_bounds__(256) void stats_kernel(const float* __restrict__ outp) {
    int warp = threadIdx.x >> 5, lane = threadIdx.x & 31;
    int row = blockIdx.x * 8 + warp;
    const float4* r4 = (const float4*)(outp + (size_t)row * C);
    float4 a[8];
    float m = -INFINITY;
#pragma unroll
    for (int i = 0; i < 8; i++) {
        int j = lane + i * 32;
        if (j < C / 4) {
            float4 x = r4[j]; a[i] = x;
            m = fmaxf(m, fmaxf(fmaxf(x.x, x.y), fmaxf(x.z, x.w)));
        }
    }
#pragma unroll
    for (int o = 16; o > 0; o >>= 1) m = fmaxf(m, __shfl_xor_sync(0xffffffffu, m, o));
    float s = 0.f;
#pragma unroll
    for (int i = 0; i < 8; i++) {
        int j = lane + i * 32;
        if (j < C / 4)
            s += __expf(a[i].x - m) + __expf(a[i].y - m) + __expf(a[i].z - m) + __expf(a[i].w - m);
    }
#pragma unroll
    for (int o = 16; o > 0; o >>= 1) s += __shfl_xor_sync(0xffffffffu, s, o);
    if (lane == 0) { g_rmax[row] = m; g_rinv[row] = 1.f / s; }
}

// ---------------- #3 (s1): pure copy out -> d_out ----------------
__global__ __launch_bounds__(256) void copy_kernel(const float* __restrict__ src,
                                                   float* __restrict__ dst) {
    size_t i = (size_t)blockIdx.x * 256 + threadIdx.x;
    size_t n4 = (size_t)B * C / 4;
    const float4* s4 = (const float4*)src;
    float4* d4 = (float4*)dst;
    for (; i < n4; i += (size_t)gridDim.x * 256) d4[i] = s4[i];
}

// ---------------- #4 (main, PROFILED): similarities via tf32 MMA ----------
// 128 rows/block, grid (128, 3). K=15 padded to 16; norms computed in fp32
// during stage loads; epilogue does avg + first-max argmax.
#define KCHUNK  32
#define ASTR    36   // A_s stride (floats): conflict-free frag LDS
#define BSTR    24   // B_s stride: conflict-free frag LDS
__global__ __launch_bounds__(256) void sim_kernel(
    const float* __restrict__ f0, const float* __restrict__ f1, const float* __restrict__ f2,
    const float* __restrict__ c0, const float* __restrict__ c1, const float* __restrict__ c2) {
    int mod = blockIdx.y;
    const float* fea = mod == 0 ? f0 : (mod == 1 ? f1 : f2);
    const float* cen = mod == 0 ? c0 : (mod == 1 ? c1 : c2);
    int tid = threadIdx.x;
    int lane = tid & 31, w = tid >> 5;
    int g = lane >> 2, tig = lane & 3;

    __shared__ unsigned As[128 * ASTR];      // 18432 B (tf32 bits)
    __shared__ unsigned Bs[KCHUNK * BSTR];   // 3072 B
    __shared__ float nrm_s[128];
    __shared__ float cns[16];
    __shared__ float cninv[16];

    int row0 = blockIdx.x * 128;

    // loader mapping: A: thread -> rows lr+{0,32,64,96}, float4 col lc
    int lr = tid >> 3;
    int lc = (tid & 7) * 4;
    // B: whole warp w loads n=w and n=w+8, kk = lane (coalesced 128B)
    int bkk = lane;

    float nacc[4] = {0.f, 0.f, 0.f, 0.f};
    float cnacc0 = 0.f, cnacc1 = 0.f;
    float cfr[2][4];
#pragma unroll
    for (int t = 0; t < 2; t++)
#pragma unroll
        for (int i = 0; i < 4; i++) cfr[t][i] = 0.f;

    // prefetch chunk 0
    float4 ar[4];
    float br0, br1;
#pragma unroll
    for (int p = 0; p < 4; p++)
        ar[p] = *(const float4*)(fea + (size_t)(row0 + lr + p * 32) * D + lc);
    br0 = cen[(size_t)w * D + bkk];
    br1 = (w + 8 < KC) ? cen[(size_t)(w + 8) * D + bkk] : 0.f;

    for (int kb = 0; kb < D; kb += KCHUNK) {
        // norms (fp32, exact) + cvt + stage
#pragma unroll
        for (int p = 0; p < 4; p++) {
            float4 v = ar[p];
            nacc[p] += v.x * v.x + v.y * v.y + v.z * v.z + v.w * v.w;
            unsigned* dst = &As[(lr + p * 32) * ASTR + lc];
            uint4 u;
            u.x = f2tf32(v.x); u.y = f2tf32(v.y); u.z = f2tf32(v.z); u.w = f2tf32(v.w);
            *(uint4*)dst = u;
        }
        cnacc0 += br0 * br0;
        cnacc1 += br1 * br1;
        Bs[bkk * BSTR + w]     = f2tf32(br0);
        Bs[bkk * BSTR + w + 8] = f2tf32(br1);
        __syncthreads();

        // prefetch next chunk
        if (kb + KCHUNK < D) {
            int nb = kb + KCHUNK;
#pragma unroll
            for (int p = 0; p < 4; p++)
                ar[p] = *(const float4*)(fea + (size_t)(row0 + lr + p * 32) * D + nb + lc);
            br0 = cen[(size_t)w * D + nb + bkk];
            br1 = (w + 8 < KC) ? cen[(size_t)(w + 8) * D + nb + bkk] : 0.f;
        }

        // 4 k-steps of m16n8k8, two n-tiles
#pragma unroll
        for (int ks = 0; ks < KCHUNK; ks += 8) {
            unsigned a0 = As[(w * 16 + g) * ASTR + ks + tig];
            unsigned a1 = As[(w * 16 + g + 8) * ASTR + ks + tig];
            unsigned a2 = As[(w * 16 + g) * ASTR + ks + tig + 4];
            unsigned a3 = As[(w * 16 + g + 8) * ASTR + ks + tig + 4];
            unsigned b0 = Bs[(ks + tig) * BSTR + g];
            unsigned b1 = Bs[(ks + tig + 4) * BSTR + g];
            mma_tf32(cfr[0], a0, a1, a2, a3, b0, b1);
            unsigned b2 = Bs[(ks + tig) * BSTR + g + 8];
            unsigned b3 = Bs[(ks + tig + 4) * BSTR + g + 8];
            mma_tf32(cfr[1], a0, a1, a2, a3, b2, b3);
        }
        __syncthreads();
    }

    // write row norms: 8 consecutive lanes share a row
#pragma unroll
    for (int p = 0; p < 4; p++) {
        float v = nacc[p];
        v += __shfl_xor_sync(0xffffffffu, v, 1);
        v += __shfl_xor_sync(0xffffffffu, v, 2);
        v += __shfl_xor_sync(0xffffffffu, v, 4);
        if ((tid & 7) == 0) nrm_s[lr + p * 32] = v;
    }
    // centroid norms: whole warp shares n
    float v0 = cnacc0, v1 = cnacc1;
#pragma unroll
    for (int o = 16; o > 0; o >>= 1) {
        v0 += __shfl_xor_sync(0xffffffffu, v0, o);
        v1 += __shfl_xor_sync(0xffffffffu, v1, o);
    }
    if (lane == 0) { cns[w] = v0; cns[w + 8] = v1; }
    __syncthreads();
    if (tid < 16) cninv[tid] = 1.f / fmaxf(sqrtf(cns[tid]), 1e-12f);
    __syncthreads();

    // epilogue: avg + first-max argmax per row
    int r_lo = w * 16 + g, r_hi = r_lo + 8;
    float fin_lo = 1.f / fmaxf(sqrtf(nrm_s[r_lo]), 1e-12f);
    float fin_hi = 1.f / fmaxf(sqrtf(nrm_s[r_hi]), 1e-12f);

    float sum_lo = 0.f, sum_hi = 0.f;
    float mx_lo = -1e30f, mx_hi = -1e30f;
    int ai_lo = 0, ai_hi = 0;
#pragma unroll
    for (int t = 0; t < 2; t++) {
        int ca = t * 8 + 2 * tig, cb = ca + 1;
        // col ca (always < 15 since ca <= 14)
        {
            float s_lo = cfr[t][0] * fin_lo * cninv[ca];
            float s_hi = cfr[t][2] * fin_hi * cninv[ca];
            sum_lo += s_lo; sum_hi += s_hi;
            if (s_lo > mx_lo) { mx_lo = s_lo; ai_lo = ca; }
            if (s_hi > mx_hi) { mx_hi = s_hi; ai_hi = ca; }
        }
        if (cb < KC) {
            float s_lo = cfr[t][1] * fin_lo * cninv[cb];
            float s_hi = cfr[t][3] * fin_hi * cninv[cb];
            sum_lo += s_lo; sum_hi += s_hi;
            if (s_lo > mx_lo) { mx_lo = s_lo; ai_lo = cb; }
            if (s_hi > mx_hi) { mx_hi = s_hi; ai_hi = cb; }
        }
    }
    // reduce across the 4-lane group (tig): sum, and max with low-index ties
#pragma unroll
    for (int o = 1; o < 4; o <<= 1) {
        sum_lo += __shfl_xor_sync(0xffffffffu, sum_lo, o);
        sum_hi += __shfl_xor_sync(0xffffffffu, sum_hi, o);
        float om_lo = __shfl_xor_sync(0xffffffffu, mx_lo, o);
        int   oa_lo = __shfl_xor_sync(0xffffffffu, ai_lo, o);
        float om_hi = __shfl_xor_sync(0xffffffffu, mx_hi, o);
        int   oa_hi = __shfl_xor_sync(0xffffffffu, ai_hi, o);
        if (om_lo > mx_lo || (om_lo == mx_lo && oa_lo < ai_lo)) { mx_lo = om_lo; ai_lo = oa_lo; }
        if (om_hi > mx_hi || (om_hi == mx_hi && oa_hi < ai_hi)) { mx_hi = om_hi; ai_hi = oa_hi; }
    }
    if (tig == 0) {
        g_avg[mod][row0 + r_lo] = sum_lo * (1.0f / KC);
        g_assign[mod][row0 + r_lo] = ai_lo;
        g_avg[mod][row0 + r_hi] = sum_hi * (1.0f / KC);
        g_assign[mod][row0 + r_hi] = ai_hi;
    }
}

// ---------------- #5 (s2): radix select + attractive (smem-resident) ------
__global__ __launch_bounds__(1024) void select_attr_kernel(int rank0) {
    extern __shared__ unsigned int skeys[];       // 16384 u32 = 64 KB
    __shared__ unsigned int hist[256];
    __shared__ unsigned int sc[256];
    __shared__ unsigned int s_prefix;
    __shared__ int s_rank;
    __shared__ float s_thr;
    __shared__ float sred[32];

    int mod = blockIdx.x;
    const float* avg = g_avg[mod];
    int tid = threadIdx.x;
    int lane = tid & 31, warp = tid >> 5;

#pragma unroll
    for (int i = tid; i < B; i += 1024) {
        unsigned int u = __float_as_uint(avg[i]);
        skeys[i] = (u & 0x80000000u) ? ~u : (u | 0x80000000u);
    }
    if (tid == 0) { s_prefix = 0u; s_rank = rank0; }
    __syncthreads();

    for (int p = 3; p >= 0; p--) {
        if (tid < 256) hist[tid] = 0u;
        __syncthreads();
        unsigned int mask = (p == 3) ? 0u : (0xFFFFFFFFu << ((p + 1) * 8));
        unsigned int pref = s_prefix;
        int r = s_rank;
#pragma unroll
        for (int i = tid; i < B; i += 1024) {
            unsigned int u = skeys[i];
            if ((u & mask) == (pref & mask))
                atomicAdd(&hist[(u >> (p * 8)) & 255u], 1u);
        }
        __syncthreads();
        if (tid < 256) sc[tid] = hist[tid];
        __syncthreads();
#pragma unroll
        for (int off = 1; off < 256; off <<= 1) {
            unsigned int add = 0u;
            if (tid < 256 && tid >= off) add = sc[tid - off];
            __syncthreads();
            if (tid < 256) sc[tid] += add;
            __syncthreads();
        }
        if (tid < 256) {
            unsigned int inc = sc[tid], exc = inc - hist[tid];
            if ((unsigned int)r >= exc && (unsigned int)r < inc) {
                s_prefix = pref | ((unsigned int)tid << (p * 8));
                s_rank = r - (int)exc;
            }
        }
        __syncthreads();
    }
    if (tid == 0) {
        unsigned int u = s_prefix;
        unsigned int bits = (u & 0x80000000u) ? (u ^ 0x80000000u) : ~u;
        s_thr = __uint_as_float(bits);
    }
    __syncthreads();

    float thr = s_thr;
    float s = 0.f;
#pragma unroll
    for (int i = tid; i < B; i += 1024) {
        unsigned int u = skeys[i];
        unsigned int bits = (u & 0x80000000u) ? (u ^ 0x80000000u) : ~u;
        float a = __uint_as_float(bits);
        float w = 1.f / (1.f + expf(-5.0f * (a - thr)));   // ALPHA = 5
        s += w * (1.f - a);
    }
#pragma unroll
    for (int o = 16; o > 0; o >>= 1) s += __shfl_xor_sync(0xffffffffu, s, o);
    if (lane == 0) sred[warp] = s;
    __syncthreads();
    if (tid < 32) {
        float t = sred[tid];
#pragma unroll
        for (int o = 16; o > 0; o >>= 1) t += __shfl_xor_sync(0xffffffffu, t, o);
        if (tid == 0) g_attrpart[mod] = t;
    }
}

// ---------------- #6 (main): segment sums, exp in-kernel, L2 atomics ------
#define SEG_CHUNK 64
__global__ __launch_bounds__(256, 4) void seg_kernel(const float* __restrict__ outp) {
    __shared__ float acc[NMOD * KC * 256];   // 46080 B
    __shared__ int   s_a0[SEG_CHUNK], s_a1[SEG_CHUNK], s_a2[SEG_CHUNK];
    __shared__ float s_rm[SEG_CHUNK], s_ri[SEG_CHUNK];
    int tid = threadIdx.x;
    int c = blockIdx.x * 256 + tid;
    bool valid = c < C;
    for (int j = tid; j < NMOD * KC * 256; j += 256) acc[j] = 0.f;

    int r0 = blockIdx.y * SEG_ROWS;
    int rend = r0 + SEG_ROWS; if (rend > B) rend = B;

    for (int cb = r0; cb < rend; cb += SEG_CHUNK) {
        int clen = rend - cb; if (clen > SEG_CHUNK) clen = SEG_CHUNK;
        __syncthreads();
        if (tid < clen) {
            s_a0[tid] = g_assign[0][cb + tid] * 256;
            s_a1[tid] = (KC + g_assign[1][cb + tid]) * 256;
            s_a2[tid] = (2 * KC + g_assign[2][cb + tid]) * 256;
            s_rm[tid] = g_rmax[cb + tid];
            s_ri[tid] = g_rinv[cb + tid];
        }
        __syncthreads();
        if (valid) {
            const float* op = outp + (size_t)cb * C + c;
            for (int rr = 0; rr < clen; rr += 8) {
                float p[8];
#pragma unroll
                for (int j = 0; j < 8; j++)
                    p[j] = op[(size_t)(rr + j) * C];
#pragma unroll
                for (int j = 0; j < 8; j++)
                    p[j] = __expf(p[j] - s_rm[rr + j]) * s_ri[rr + j];
#pragma unroll
                for (int j = 0; j < 8; j++) {
                    acc[s_a0[rr + j] + tid] += p[j];
                    acc[s_a1[rr + j] + tid] += p[j];
                    acc[s_a2[rr + j] + tid] += p[j];
                }
            }
        }
    }
    __syncthreads();
    if (valid) {
#pragma unroll
        for (int j = 0; j < NMOD * KC; j++)
            atomicAdd(&g_segsum[j][c], acc[j * 256 + tid]);
    }
}

// ---------------- #7 (main): entropy + counts + finalize (ticket) ---------
__global__ void entropy_final_kernel(float* dout_last) {
    int bk = blockIdx.x;  // 0..44
    int mod = bk / KC, k = bk % KC;
    int tid = threadIdx.x;

    int cnt = 0;
    const int* as = g_assign[mod];
    for (int i = tid; i < B; i += 256) cnt += (as[i] == k);
    __shared__ int ci[256];
    ci[tid] = cnt; __syncthreads();
    for (int o = 128; o > 0; o >>= 1) {
        if (tid < o) ci[tid] += ci[tid + o];
        __syncthreads();
    }
    float fcnt = (float)ci[0];
    float inv = 1.f / fmaxf(fcnt, 1.f);

    float s = 0.f;
    for (int i = tid; i < C; i += 256) {
        float mp = g_segsum[bk][i] * inv;
        s += mp * __logf(mp + 1e-8f);
    }
    __shared__ float sm[256];
    sm[tid] = s; __syncthreads();
    for (int o = 128; o > 0; o >>= 1) {
        if (tid < o) sm[tid] += sm[tid + o];
        __syncthreads();
    }
    if (tid == 0) {
        g_entpart[bk] = (fcnt >= 3.0f) ? sm[0] : 0.f;
        __threadfence();
        int t = atomicAdd(&g_ticket, 1);
        if (t == NMOD * KC - 1) {
            __threadfence();
            float div = 0.f;
#pragma unroll
            for (int j = 0; j < NMOD * KC; j++) div += g_entpart[j];
            float attr = g_attrpart[0] + g_attrpart[1] + g_attrpart[2];
            // LAM_CLUSTER = 6.0, LAM_DIV = 0.1
            *dout_last = 6.0f * (attr / (float)B) + 0.1f * div;
        }
    }
}

// ---------------- launch: fork-join multi-stream graph --------------------
extern "C" void kernel_launch(void* const* d_in, const int* in_sizes, int n_in,
                              void* d_out, int out_size) {
    const float* f0 = (const float*)d_in[0];
    const float* f1 = (const float*)d_in[1];
    const float* f2 = (const float*)d_in[2];
    const float* c0 = (const float*)d_in[3];
    const float* c1 = (const float*)d_in[4];
    const float* c2 = (const float*)d_in[5];
    const float* outp = (const float*)d_in[6];
    float* dout = (float*)d_out;
    (void)n_in; (void)in_sizes;

    static cudaStream_t s1 = 0, s2 = 0;
    static cudaEvent_t ev_root = 0, ev_stats = 0, ev_copy = 0, ev_sim = 0, ev_sel = 0;
    if (s1 == 0) {
        cudaStreamCreateWithFlags(&s1, cudaStreamNonBlocking);
        cudaStreamCreateWithFlags(&s2, cudaStreamNonBlocking);
        cudaEventCreateWithFlags(&ev_root, cudaEventDisableTiming);
        cudaEventCreateWithFlags(&ev_stats, cudaEventDisableTiming);
        cudaEventCreateWithFlags(&ev_copy, cudaEventDisableTiming);
        cudaEventCreateWithFlags(&ev_sim, cudaEventDisableTiming);
        cudaEventCreateWithFlags(&ev_sel, cudaEventDisableTiming);
        cudaFuncSetAttribute(select_attr_kernel,
                             cudaFuncAttributeMaxDynamicSharedMemorySize, B * 4);
    }

    // fork to s1: init + stats + copy (independent of sim)
    cudaEventRecord(ev_root, 0);
    cudaStreamWaitEvent(s1, ev_root, 0);
    init_kernel<<<(NMOD * KC * C + 255) / 256, 256, 0, s1>>>();             // #1
    stats_kernel<<<B / 8, 256, 0, s1>>>(outp);                              // #2
    cudaEventRecord(ev_stats, s1);
    copy_kernel<<<2048, 256, 0, s1>>>(outp, dout);                          // #3
    cudaEventRecord(ev_copy, s1);

    // main: sim via tf32 MMA (profiled slot #4)
    sim_kernel<<<dim3(B / 128, NMOD), 256>>>(f0, f1, f2, c0, c1, c2);       // #4

    // fork to s2: select (depends only on sim)
    cudaEventRecord(ev_sim, 0);
    cudaStreamWaitEvent(s2, ev_sim, 0);
    int rank0 = B - (int)((double)B * 0.6);   // = 6554
    select_attr_kernel<<<NMOD, 1024, B * 4, s2>>>(rank0);                   // #5
    cudaEventRecord(ev_sel, s2);

    // main: seg needs stats(+init) + assigns(sim, same stream)
    cudaStreamWaitEvent(0, ev_stats, 0);
    seg_kernel<<<dim3(4, 148), 256>>>(outp);                                // #6

    // join select + copy, then entropy+finalize
    cudaStreamWaitEvent(0, ev_sel, 0);
    cudaStreamWaitEvent(0, ev_copy, 0);
    entropy_final_kernel<<<NMOD * KC, 256>>>(dout + (size_t)out_size - 1);  // #7
}

// round 11
// speedup vs baseline: 2.2055x; 1.1319x over previous
#include <cuda_runtime.h>
#include <math.h>

#define B    16384
#define D    1024
#define KC   15
#define C    1000
#define NMOD 3

#define SEG_ROWS 112   // grid (4,148): 148*112 = 16576 >= B

// ---------------- scratch (device globals; no allocation) ----------------
__device__ float g_avg[NMOD][B];
__device__ int   g_assign[NMOD][B];
__device__ float g_rmax[B];
__device__ float g_rinv[B];
__device__ float g_segsum[NMOD * KC][C];   // 180 KB, L2-resident
__device__ float g_entpart[NMOD * KC];
__device__ float g_attrpart[NMOD];
__device__ int   g_ticket;

__device__ __forceinline__ unsigned f2tf32(float x) {
    unsigned r; asm("cvt.rna.tf32.f32 %0, %1;" : "=r"(r) : "f"(x)); return r;
}
__device__ __forceinline__ void mma_tf32(float c[4], unsigned a0, unsigned a1,
                                         unsigned a2, unsigned a3,
                                         unsigned b0, unsigned b1) {
    asm volatile(
        "mma.sync.aligned.m16n8k8.row.col.f32.tf32.tf32.f32 "
        "{%0,%1,%2,%3}, {%4,%5,%6,%7}, {%8,%9}, {%0,%1,%2,%3};\n"
        : "+f"(c[0]), "+f"(c[1]), "+f"(c[2]), "+f"(c[3])
        : "r"(a0), "r"(a1), "r"(a2), "r"(a3), "r"(b0), "r"(b1));
}

// ---------------- #1 (s1): zero segsum + ticket ----------------
__global__ void init_kernel() {
    int i = blockIdx.x * blockDim.x + threadIdx.x;
    if (i < NMOD * KC * C) ((float*)g_segsum)[i] = 0.f;
    if (i == 0) g_ticket = 0;
}

// ---------------- #2 (s1): softmax stats only ----------------
__global__ __launch_bounds__(256) void stats_kernel(const float* __restrict__ outp) {
    int warp = threadIdx.x >> 5, lane = threadIdx.x & 31;
    int row = blockIdx.x * 8 + warp;
    const float4* r4 = (const float4*)(outp + (size_t)row * C);
    float4 a[8];
    float m = -INFINITY;
#pragma unroll
    for (int i = 0; i < 8; i++) {
        int j = lane + i * 32;
        if (j < C / 4) {
            float4 x = r4[j]; a[i] = x;
            m = fmaxf(m, fmaxf(fmaxf(x.x, x.y), fmaxf(x.z, x.w)));
        }
    }
#pragma unroll
    for (int o = 16; o > 0; o >>= 1) m = fmaxf(m, __shfl_xor_sync(0xffffffffu, m, o));
    float s = 0.f;
#pragma unroll
    for (int i = 0; i < 8; i++) {
        int j = lane + i * 32;
        if (j < C / 4)
            s += __expf(a[i].x - m) + __expf(a[i].y - m) + __expf(a[i].z - m) + __expf(a[i].w - m);
    }
#pragma unroll
    for (int o = 16; o > 0; o >>= 1) s += __shfl_xor_sync(0xffffffffu, s, o);
    if (lane == 0) { g_rmax[row] = m; g_rinv[row] = 1.f / s; }
}

// ---------------- #3 (s1): pure copy out -> d_out ----------------
__global__ __launch_bounds__(256) void copy_kernel(const float* __restrict__ src,
                                                   float* __restrict__ dst) {
    size_t i = (size_t)blockIdx.x * 256 + threadIdx.x;
    size_t n4 = (size_t)B * C / 4;
    const float4* s4 = (const float4*)src;
    float4* d4 = (float4*)dst;
    for (; i < n4; i += (size_t)gridDim.x * 256) d4[i] = s4[i];
}

// ---------------- #4 (main, PROFILED): similarities via tf32 MMA ----------
// 128 rows/block, grid (128, 3). KCHUNK=64: 8 float4 prefetch regs in flight.
#define KCHUNK  64
#define ASTR    68   // 68 mod 32 == 4: conflict-free frag LDS (banks 4g+tig)
#define BSTR    24
__global__ __launch_bounds__(256) void sim_kernel(
    const float* __restrict__ f0, const float* __restrict__ f1, const float* __restrict__ f2,
    const float* __restrict__ c0, const float* __restrict__ c1, const float* __restrict__ c2) {
    int mod = blockIdx.y;
    const float* fea = mod == 0 ? f0 : (mod == 1 ? f1 : f2);
    const float* cen = mod == 0 ? c0 : (mod == 1 ? c1 : c2);
    int tid = threadIdx.x;
    int lane = tid & 31, w = tid >> 5;
    int g = lane >> 2, tig = lane & 3;

    __shared__ unsigned As[128 * ASTR];      // 34816 B
    __shared__ unsigned Bs[KCHUNK * BSTR];   // 6144 B
    __shared__ float nrm_s[128];
    __shared__ float cns[16];
    __shared__ float cninv[16];

    int row0 = blockIdx.x * 128;

    // A loader: thread -> rows lr + p*16 (p=0..7), float4 col lc (64 cols)
    int lr = tid >> 4;
    int lc = (tid & 15) * 4;
    // B loader: warp w loads n=w and n=w+8, kk = lane and lane+32
    int bkk = lane;

    float nacc[8] = {0.f, 0.f, 0.f, 0.f, 0.f, 0.f, 0.f, 0.f};
    float cnacc0 = 0.f, cnacc1 = 0.f;
    float cfr[2][4];
#pragma unroll
    for (int t = 0; t < 2; t++)
#pragma unroll
        for (int i = 0; i < 4; i++) cfr[t][i] = 0.f;

    // prefetch chunk 0
    float4 ar[8];
    float br0a, br0b, br1a, br1b;
#pragma unroll
    for (int p = 0; p < 8; p++)
        ar[p] = *(const float4*)(fea + (size_t)(row0 + lr + p * 16) * D + lc);
    br0a = cen[(size_t)w * D + bkk];
    br0b = cen[(size_t)w * D + bkk + 32];
    br1a = (w + 8 < KC) ? cen[(size_t)(w + 8) * D + bkk] : 0.f;
    br1b = (w + 8 < KC) ? cen[(size_t)(w + 8) * D + bkk + 32] : 0.f;

    for (int kb = 0; kb < D; kb += KCHUNK) {
        // norms (fp32, exact) + cvt + stage
#pragma unroll
        for (int p = 0; p < 8; p++) {
            float4 v = ar[p];
            nacc[p] += v.x * v.x + v.y * v.y + v.z * v.z + v.w * v.w;
            unsigned* dst = &As[(lr + p * 16) * ASTR + lc];
            uint4 u;
            u.x = f2tf32(v.x); u.y = f2tf32(v.y); u.z = f2tf32(v.z); u.w = f2tf32(v.w);
            *(uint4*)dst = u;
        }
        cnacc0 += br0a * br0a + br0b * br0b;
        cnacc1 += br1a * br1a + br1b * br1b;
        Bs[bkk * BSTR + w]            = f2tf32(br0a);
        Bs[(bkk + 32) * BSTR + w]     = f2tf32(br0b);
        Bs[bkk * BSTR + w + 8]        = f2tf32(br1a);
        Bs[(bkk + 32) * BSTR + w + 8] = f2tf32(br1b);
        __syncthreads();

        // prefetch next chunk (8 LDG.128 in flight through the mma section)
        if (kb + KCHUNK < D) {
            int nb = kb + KCHUNK;
#pragma unroll
            for (int p = 0; p < 8; p++)
                ar[p] = *(const float4*)(fea + (size_t)(row0 + lr + p * 16) * D + nb + lc);
            br0a = cen[(size_t)w * D + nb + bkk];
            br0b = cen[(size_t)w * D + nb + bkk + 32];
            br1a = (w + 8 < KC) ? cen[(size_t)(w + 8) * D + nb + bkk] : 0.f;
            br1b = (w + 8 < KC) ? cen[(size_t)(w + 8) * D + nb + bkk + 32] : 0.f;
        }

        // 8 k-steps of m16n8k8, two n-tiles
#pragma unroll
        for (int ks = 0; ks < KCHUNK; ks += 8) {
            unsigned a0 = As[(w * 16 + g) * ASTR + ks + tig];
            unsigned a1 = As[(w * 16 + g + 8) * ASTR + ks + tig];
            unsigned a2 = As[(w * 16 + g) * ASTR + ks + tig + 4];
            unsigned a3 = As[(w * 16 + g + 8) * ASTR + ks + tig + 4];
            unsigned b0 = Bs[(ks + tig) * BSTR + g];
            unsigned b1 = Bs[(ks + tig + 4) * BSTR + g];
            mma_tf32(cfr[0], a0, a1, a2, a3, b0, b1);
            unsigned b2 = Bs[(ks + tig) * BSTR + g + 8];
            unsigned b3 = Bs[(ks + tig + 4) * BSTR + g + 8];
            mma_tf32(cfr[1], a0, a1, a2, a3, b2, b3);
        }
        __syncthreads();
    }

    // row norms: 16 consecutive lanes (tid&15) share... reduce across lanes
    // sharing the same row: threads with same (tid>>4) differ in (tid&15);
    // within a warp that's lanes l and l+16 pairs plus 4-wide groups.
#pragma unroll
    for (int p = 0; p < 8; p++) {
        float v = nacc[p];
        v += __shfl_xor_sync(0xffffffffu, v, 1);
        v += __shfl_xor_sync(0xffffffffu, v, 2);
        v += __shfl_xor_sync(0xffffffffu, v, 4);
        v += __shfl_xor_sync(0xffffffffu, v, 8);
        if ((tid & 15) == 0) nrm_s[lr + p * 16] = v;
    }
    float v0 = cnacc0, v1 = cnacc1;
#pragma unroll
    for (int o = 16; o > 0; o >>= 1) {
        v0 += __shfl_xor_sync(0xffffffffu, v0, o);
        v1 += __shfl_xor_sync(0xffffffffu, v1, o);
    }
    if (lane == 0) { cns[w] = v0; cns[w + 8] = v1; }
    __syncthreads();
    if (tid < 16) cninv[tid] = 1.f / fmaxf(sqrtf(cns[tid]), 1e-12f);
    __syncthreads();

    // epilogue: avg + first-max argmax per row
    int r_lo = w * 16 + g, r_hi = r_lo + 8;
    float fin_lo = 1.f / fmaxf(sqrtf(nrm_s[r_lo]), 1e-12f);
    float fin_hi = 1.f / fmaxf(sqrtf(nrm_s[r_hi]), 1e-12f);

    float sum_lo = 0.f, sum_hi = 0.f;
    float mx_lo = -1e30f, mx_hi = -1e30f;
    int ai_lo = 0, ai_hi = 0;
#pragma unroll
    for (int t = 0; t < 2; t++) {
        int ca = t * 8 + 2 * tig, cb = ca + 1;
        {
            float s_lo = cfr[t][0] * fin_lo * cninv[ca];
            float s_hi = cfr[t][2] * fin_hi * cninv[ca];
            sum_lo += s_lo; sum_hi += s_hi;
            if (s_lo > mx_lo) { mx_lo = s_lo; ai_lo = ca; }
            if (s_hi > mx_hi) { mx_hi = s_hi; ai_hi = ca; }
        }
        if (cb < KC) {
            float s_lo = cfr[t][1] * fin_lo * cninv[cb];
            float s_hi = cfr[t][3] * fin_hi * cninv[cb];
            sum_lo += s_lo; sum_hi += s_hi;
            if (s_lo > mx_lo) { mx_lo = s_lo; ai_lo = cb; }
            if (s_hi > mx_hi) { mx_hi = s_hi; ai_hi = cb; }
        }
    }
#pragma unroll
    for (int o = 1; o < 4; o <<= 1) {
        sum_lo += __shfl_xor_sync(0xffffffffu, sum_lo, o);
        sum_hi += __shfl_xor_sync(0xffffffffu, sum_hi, o);
        float om_lo = __shfl_xor_sync(0xffffffffu, mx_lo, o);
        int   oa_lo = __shfl_xor_sync(0xffffffffu, ai_lo, o);
        float om_hi = __shfl_xor_sync(0xffffffffu, mx_hi, o);
        int   oa_hi = __shfl_xor_sync(0xffffffffu, ai_hi, o);
        if (om_lo > mx_lo || (om_lo == mx_lo && oa_lo < ai_lo)) { mx_lo = om_lo; ai_lo = oa_lo; }
        if (om_hi > mx_hi || (om_hi == mx_hi && oa_hi < ai_hi)) { mx_hi = om_hi; ai_hi = oa_hi; }
    }
    if (tig == 0) {
        g_avg[mod][row0 + r_lo] = sum_lo * (1.0f / KC);
        g_assign[mod][row0 + r_lo] = ai_lo;
        g_avg[mod][row0 + r_hi] = sum_hi * (1.0f / KC);
        g_assign[mod][row0 + r_hi] = ai_hi;
    }
}

// ---------------- #5 (s2): radix select + attractive (smem-resident) ------
__global__ __launch_bounds__(1024) void select_attr_kernel(int rank0) {
    extern __shared__ unsigned int skeys[];       // 16384 u32 = 64 KB
    __shared__ unsigned int hist[256];
    __shared__ unsigned int sc[256];
    __shared__ unsigned int s_prefix;
    __shared__ int s_rank;
    __shared__ float s_thr;
    __shared__ float sred[32];

    int mod = blockIdx.x;
    const float* avg = g_avg[mod];
    int tid = threadIdx.x;
    int lane = tid & 31, warp = tid >> 5;

#pragma unroll
    for (int i = tid; i < B; i += 1024) {
        unsigned int u = __float_as_uint(avg[i]);
        skeys[i] = (u & 0x80000000u) ? ~u : (u | 0x80000000u);
    }
    if (tid == 0) { s_prefix = 0u; s_rank = rank0; }
    __syncthreads();

    for (int p = 3; p >= 0; p--) {
        if (tid < 256) hist[tid] = 0u;
        __syncthreads();
        unsigned int mask = (p == 3) ? 0u : (0xFFFFFFFFu << ((p + 1) * 8));
        unsigned int pref = s_prefix;
        int r = s_rank;
#pragma unroll
        for (int i = tid; i < B; i += 1024) {
            unsigned int u = skeys[i];
            if ((u & mask) == (pref & mask))
                atomicAdd(&hist[(u >> (p * 8)) & 255u], 1u);
        }
        __syncthreads();
        if (tid < 256) sc[tid] = hist[tid];
        __syncthreads();
#pragma unroll
        for (int off = 1; off < 256; off <<= 1) {
            unsigned int add = 0u;
            if (tid < 256 && tid >= off) add = sc[tid - off];
            __syncthreads();
            if (tid < 256) sc[tid] += add;
            __syncthreads();
        }
        if (tid < 256) {
            unsigned int inc = sc[tid], exc = inc - hist[tid];
            if ((unsigned int)r >= exc && (unsigned int)r < inc) {
                s_prefix = pref | ((unsigned int)tid << (p * 8));
                s_rank = r - (int)exc;
            }
        }
        __syncthreads();
    }
    if (tid == 0) {
        unsigned int u = s_prefix;
        unsigned int bits = (u & 0x80000000u) ? (u ^ 0x80000000u) : ~u;
        s_thr = __uint_as_float(bits);
    }
    __syncthreads();

    float thr = s_thr;
    float s = 0.f;
#pragma unroll
    for (int i = tid; i < B; i += 1024) {
        unsigned int u = skeys[i];
        unsigned int bits = (u & 0x80000000u) ? (u ^ 0x80000000u) : ~u;
        float a = __uint_as_float(bits);
        float w = 1.f / (1.f + expf(-5.0f * (a - thr)));   // ALPHA = 5
        s += w * (1.f - a);
    }
#pragma unroll
    for (int o = 16; o > 0; o >>= 1) s += __shfl_xor_sync(0xffffffffu, s, o);
    if (lane == 0) sred[warp] = s;
    __syncthreads();
    if (tid < 32) {
        float t = sred[tid];
#pragma unroll
        for (int o = 16; o > 0; o >>= 1) t += __shfl_xor_sync(0xffffffffu, t, o);
        if (tid == 0) g_attrpart[mod] = t;
    }
}

// ---------------- #6 (main): segment sums, 16-row unroll, L2 atomics ------
#define SEG_CHUNK 64
__global__ __launch_bounds__(256, 4) void seg_kernel(const float* __restrict__ outp) {
    __shared__ float acc[NMOD * KC * 256];   // 46080 B
    __shared__ int   s_a0[SEG_CHUNK], s_a1[SEG_CHUNK], s_a2[SEG_CHUNK];
    __shared__ float s_rm[SEG_CHUNK], s_ri[SEG_CHUNK];
    int tid = threadIdx.x;
    int c = blockIdx.x * 256 + tid;
    bool valid = c < C;
    for (int j = tid; j < NMOD * KC * 256; j += 256) acc[j] = 0.f;

    int r0 = blockIdx.y * SEG_ROWS;
    int rend = r0 + SEG_ROWS; if (rend > B) rend = B;

    for (int cb = r0; cb < rend; cb += SEG_CHUNK) {
        int clen = rend - cb; if (clen > SEG_CHUNK) clen = SEG_CHUNK;  // mult of 16
        __syncthreads();
        if (tid < clen) {
            s_a0[tid] = g_assign[0][cb + tid] * 256;
            s_a1[tid] = (KC + g_assign[1][cb + tid]) * 256;
            s_a2[tid] = (2 * KC + g_assign[2][cb + tid]) * 256;
            s_rm[tid] = g_rmax[cb + tid];
            s_ri[tid] = g_rinv[cb + tid];
        }
        __syncthreads();
        if (valid) {
            const float* op = outp + (size_t)cb * C + c;
            for (int rr = 0; rr < clen; rr += 16) {
                float p[16];
#pragma unroll
                for (int j = 0; j < 16; j++)
                    p[j] = op[(size_t)(rr + j) * C];           // 16 loads in flight
#pragma unroll
                for (int j = 0; j < 16; j++)
                    p[j] = __expf(p[j] - s_rm[rr + j]) * s_ri[rr + j];
#pragma unroll
                for (int j = 0; j < 16; j++) {
                    acc[s_a0[rr + j] + tid] += p[j];
                    acc[s_a1[rr + j] + tid] += p[j];
                    acc[s_a2[rr + j] + tid] += p[j];
                }
            }
        }
    }
    __syncthreads();
    if (valid) {
#pragma unroll
        for (int j = 0; j < NMOD * KC; j++)
            atomicAdd(&g_segsum[j][c], acc[j * 256 + tid]);
    }
}

// ---------------- #7 (main): entropy + counts + finalize (ticket) ---------
__global__ void entropy_final_kernel(float* dout_last) {
    int bk = blockIdx.x;  // 0..44
    int mod = bk / KC, k = bk % KC;
    int tid = threadIdx.x;

    int cnt = 0;
    const int* as = g_assign[mod];
    for (int i = tid; i < B; i += 256) cnt += (as[i] == k);
    __shared__ int ci[256];
    ci[tid] = cnt; __syncthreads();
    for (int o = 128; o > 0; o >>= 1) {
        if (tid < o) ci[tid] += ci[tid + o];
        __syncthreads();
    }
    float fcnt = (float)ci[0];
    float inv = 1.f / fmaxf(fcnt, 1.f);

    float s = 0.f;
    for (int i = tid; i < C; i += 256) {
        float mp = g_segsum[bk][i] * inv;
        s += mp * __logf(mp + 1e-8f);
    }
    __shared__ float sm[256];
    sm[tid] = s; __syncthreads();
    for (int o = 128; o > 0; o >>= 1) {
        if (tid < o) sm[tid] += sm[tid + o];
        __syncthreads();
    }
    if (tid == 0) {
        g_entpart[bk] = (fcnt >= 3.0f) ? sm[0] : 0.f;
        __threadfence();
        int t = atomicAdd(&g_ticket, 1);
        if (t == NMOD * KC - 1) {
            __threadfence();
            float div = 0.f;
#pragma unroll
            for (int j = 0; j < NMOD * KC; j++) div += g_entpart[j];
            float attr = g_attrpart[0] + g_attrpart[1] + g_attrpart[2];
            // LAM_CLUSTER = 6.0, LAM_DIV = 0.1
            *dout_last = 6.0f * (attr / (float)B) + 0.1f * div;
        }
    }
}

// ---------------- launch: fork-join multi-stream graph --------------------
extern "C" void kernel_launch(void* const* d_in, const int* in_sizes, int n_in,
                              void* d_out, int out_size) {
    const float* f0 = (const float*)d_in[0];
    const float* f1 = (const float*)d_in[1];
    const float* f2 = (const float*)d_in[2];
    const float* c0 = (const float*)d_in[3];
    const float* c1 = (const float*)d_in[4];
    const float* c2 = (const float*)d_in[5];
    const float* outp = (const float*)d_in[6];
    float* dout = (float*)d_out;
    (void)n_in; (void)in_sizes;

    static cudaStream_t s1 = 0, s2 = 0;
    static cudaEvent_t ev_root = 0, ev_stats = 0, ev_copy = 0, ev_sim = 0, ev_sel = 0;
    if (s1 == 0) {
        cudaStreamCreateWithFlags(&s1, cudaStreamNonBlocking);
        cudaStreamCreateWithFlags(&s2, cudaStreamNonBlocking);
        cudaEventCreateWithFlags(&ev_root, cudaEventDisableTiming);
        cudaEventCreateWithFlags(&ev_stats, cudaEventDisableTiming);
        cudaEventCreateWithFlags(&ev_copy, cudaEventDisableTiming);
        cudaEventCreateWithFlags(&ev_sim, cudaEventDisableTiming);
        cudaEventCreateWithFlags(&ev_sel, cudaEventDisableTiming);
        cudaFuncSetAttribute(select_attr_kernel,
                             cudaFuncAttributeMaxDynamicSharedMemorySize, B * 4);
    }

    // fork to s1: init + stats + copy (independent of sim)
    cudaEventRecord(ev_root, 0);
    cudaStreamWaitEvent(s1, ev_root, 0);
    init_kernel<<<(NMOD * KC * C + 255) / 256, 256, 0, s1>>>();             // #1
    stats_kernel<<<B / 8, 256, 0, s1>>>(outp);                              // #2
    cudaEventRecord(ev_stats, s1);
    copy_kernel<<<2048, 256, 0, s1>>>(outp, dout);                          // #3
    cudaEventRecord(ev_copy, s1);

    // main: sim via tf32 MMA (profiled slot #4)
    sim_kernel<<<dim3(B / 128, NMOD), 256>>>(f0, f1, f2, c0, c1, c2);       // #4

    // fork to s2: select (depends only on sim)
    cudaEventRecord(ev_sim, 0);
    cudaStreamWaitEvent(s2, ev_sim, 0);
    int rank0 = B - (int)((double)B * 0.6);   // = 6554
    select_attr_kernel<<<NMOD, 1024, B * 4, s2>>>(rank0);                   // #5
    cudaEventRecord(ev_sel, s2);

    // main: seg needs stats(+init) + assigns(sim, same stream)
    cudaStreamWaitEvent(0, ev_stats, 0);
    seg_kernel<<<dim3(4, 148), 256>>>(outp);                                // #6

    // join select + copy, then entropy+finalize
    cudaStreamWaitEvent(0, ev_sel, 0);
    cudaStreamWaitEvent(0, ev_copy, 0);
    entropy_final_kernel<<<NMOD * KC, 256>>>(dout + (size_t)out_size - 1);  // #7
}